// round 3
// baseline (speedup 1.0000x reference)
#include <cuda_runtime.h>
#include <math.h>

#define N_TOKENS 65536
#define EMB_DIM  128
#define NUM_EMB  1024

// Output tuple flattened scalar-wise in reference-return order:
// (e_latent_loss, quantized_st[N,D], perplexity, encodings[N,K])
#define OUT_LOSS 0
#define OUT_Q    1
#define OUT_PERP (1 + N_TOKENS * EMB_DIM)        // 8388609
#define OUT_ENC  (2 + N_TOKENS * EMB_DIM)        // 8388610  (8B-aligned only)

#define BM 128
#define BN 128
#define BK 32
#define SAS (BM + 4)   // padded smem stride (132) to break STS bank conflicts
#define NBLK (N_TOKENS / BM)   // 512

__device__ float  g_be[NUM_EMB];     // fl32 of exact ||e_k||^2
__device__ float  g_sx[N_TOKENS];    // fl32 of exact ||x_n||^2
__device__ int    g_hist[NUM_EMB];   // code counts
__device__ double g_lpart[NBLK];     // per-block loss partials (deterministic)

// ---------------------------------------------------------------------------
// prep: codebook squared norms (double -> fl32; order-insensitive by the
// whole-ulp shift-invariance argument) + zero histogram
// ---------------------------------------------------------------------------
__global__ void vq_prep_kernel(const float* __restrict__ emb) {
    int k = blockIdx.x * blockDim.x + threadIdx.x;
    if (k < NUM_EMB) {
        const float* e = emb + (size_t)k * EMB_DIM;
        double s = 0.0;
#pragma unroll
        for (int i = 0; i < EMB_DIM; i++) {
            double v = (double)e[i];
            s += v * v;
        }
        g_be[k]   = (float)s;
        g_hist[k] = 0;
    }
}

// ---------------------------------------------------------------------------
// per-token squared norms, double accumulation (order-insensitive), warp/row
// ---------------------------------------------------------------------------
__global__ void vq_sx_kernel(const float* __restrict__ x) {
    const int row  = blockIdx.x * 8 + (threadIdx.x >> 5);
    const int lane = threadIdx.x & 31;
    const float* xr = x + (size_t)row * EMB_DIM;
    double s = 0.0;
#pragma unroll
    for (int i = 0; i < 4; i++) {
        double v = (double)xr[lane + 32 * i];
        s += v * v;
    }
#pragma unroll
    for (int off = 16; off > 0; off >>= 1)
        s += __shfl_down_sync(0xffffffffu, s, off);
    if (lane == 0) g_sx[row] = (float)s;
}

// ---------------------------------------------------------------------------
// main: tiled fp32 GEMM (x @ emb^T), each dot a strict sequential fp32 FMA
// chain over k ascending (matches Eigen gebp / cuBLAS SGEMM accumulation).
// Distance replicates reference rounding exactly:
//   d_k = fl32( fl32(sx + se_k) - fl32(2 * dot_k) )
// argmin with first-index tie-break, then cooperative coalesced epilogue.
// ---------------------------------------------------------------------------
__global__ __launch_bounds__(256, 2)
void vq_main_kernel(const float* __restrict__ x,
                    const float* __restrict__ emb,
                    float* __restrict__ out)
{
    __shared__ __align__(16) float smembuf[2 * BK * SAS];  // 33792 B
    float* sA = smembuf;               // [BK][SAS]  x tile (k-major)
    float* sB = smembuf + BK * SAS;    // [BK][SAS]  emb tile (k-major)

    const int tid = threadIdx.x;       // 256 threads
    const int tx  = tid & 15;          // 0..15  -> 8 codes each
    const int ty  = tid >> 4;          // 0..15  -> 8 tokens each
    const int m0  = blockIdx.x * BM;

    const int lr = tid >> 3;           // 0..31 : row within load pass
    const int lc = tid & 7;            // 0..7  : float4 column

    // ---- zero this block's one-hot region early (overlaps with GEMM) ----
    {
        float2* enc2 = (float2*)(out + OUT_ENC);   // OUT_ENC is even -> 8B ok
        size_t base = (size_t)m0 * (NUM_EMB / 2);
#pragma unroll 4
        for (int i = tid; i < BM * NUM_EMB / 2; i += 256)
            enc2[base + i] = make_float2(0.f, 0.f);
    }

    const float4* x4 = (const float4*)x;
    const float4* e4 = (const float4*)emb;

    // per-thread token rows: m0 + ty*8 + i
    float sxr[8];
#pragma unroll
    for (int i = 0; i < 8; i++) sxr[i] = g_sx[m0 + ty * 8 + i];

    float rmin[8];
    int   ridx[8];
#pragma unroll
    for (int i = 0; i < 8; i++) { rmin[i] = INFINITY; ridx[i] = 0; }

    for (int ct = 0; ct < NUM_EMB / BN; ct++) {   // 8 code tiles, k0 ascending
        const int k0 = ct * BN;
        float acc[8][8];
#pragma unroll
        for (int i = 0; i < 8; i++)
#pragma unroll
            for (int j = 0; j < 8; j++) acc[i][j] = 0.f;

        for (int ks = 0; ks < EMB_DIM / BK; ks++) {   // 4 depth steps, ascending
            __syncthreads();
#pragma unroll
            for (int p = 0; p < 4; p++) {
                int r = p * 32 + lr;
                float4 va = x4[(size_t)(m0 + r) * (EMB_DIM / 4) + ks * 8 + lc];
                float4 vb = e4[(size_t)(k0 + r) * (EMB_DIM / 4) + ks * 8 + lc];
                int kk = lc * 4;
                sA[(kk + 0) * SAS + r] = va.x;
                sA[(kk + 1) * SAS + r] = va.y;
                sA[(kk + 2) * SAS + r] = va.z;
                sA[(kk + 3) * SAS + r] = va.w;
                sB[(kk + 0) * SAS + r] = vb.x;
                sB[(kk + 1) * SAS + r] = vb.y;
                sB[(kk + 2) * SAS + r] = vb.z;
                sB[(kk + 3) * SAS + r] = vb.w;
            }
            __syncthreads();

#pragma unroll
            for (int k = 0; k < BK; k++) {   // strictly ascending k per acc
                float a[8], b[8];
                float4 a0 = *(const float4*)&sA[k * SAS + ty * 8];
                float4 a1 = *(const float4*)&sA[k * SAS + ty * 8 + 4];
                float4 b0 = *(const float4*)&sB[k * SAS + tx * 8];
                float4 b1 = *(const float4*)&sB[k * SAS + tx * 8 + 4];
                a[0] = a0.x; a[1] = a0.y; a[2] = a0.z; a[3] = a0.w;
                a[4] = a1.x; a[5] = a1.y; a[6] = a1.z; a[7] = a1.w;
                b[0] = b0.x; b[1] = b0.y; b[2] = b0.z; b[3] = b0.w;
                b[4] = b1.x; b[5] = b1.y; b[6] = b1.z; b[7] = b1.w;
#pragma unroll
                for (int i = 0; i < 8; i++)
#pragma unroll
                    for (int j = 0; j < 8; j++)
                        acc[i][j] = __fmaf_rn(a[i], b[j], acc[i][j]);
            }
        }

        // fold this code tile into the running per-row min, reference rounding:
        //   d = fl( fl(sx + se_k) - fl(2*dot) );  j ascending => first-index ties
#pragma unroll
        for (int j = 0; j < 8; j++) {
            const int kk  = k0 + tx * 8 + j;
            const float bek = g_be[kk];
#pragma unroll
            for (int i = 0; i < 8; i++) {
                float A = __fadd_rn(sxr[i], bek);
                float d = __fsub_rn(A, __fmul_rn(2.0f, acc[i][j]));
                if (d < rmin[i]) { rmin[i] = d; ridx[i] = kk; }
            }
        }
    }

    // -------- cross-thread argmin reduction (16 threads per row) --------
    __syncthreads();
    float*  redv = (float*)smembuf;                               // [0, 8192)
    int*    redi = (int*)   ((char*)smembuf + 8192);              // [8192, 16384)
    int*    s_bk = (int*)   ((char*)smembuf + 16384);             // [16384, 16896)
    double* lred = (double*)((char*)smembuf + 16896);             // [16896, 18944)
#pragma unroll
    for (int i = 0; i < 8; i++) {
        redv[(ty * 8 + i) * 16 + tx] = rmin[i];
        redi[(ty * 8 + i) * 16 + tx] = ridx[i];
    }
    __syncthreads();

    if (tid < 128) {
        float bv = redv[tid * 16];
        int   bk = redi[tid * 16];
#pragma unroll
        for (int t = 1; t < 16; t++) {
            float v  = redv[tid * 16 + t];
            int   kk = redi[tid * 16 + t];
            if (v < bv || (v == bv && kk < bk)) { bv = v; bk = kk; }
        }
        s_bk[tid] = bk;
        const int row = m0 + tid;
        // one-hot (region zeroed at block start; __syncthreads ordered)
        out[(size_t)OUT_ENC + (size_t)row * NUM_EMB + bk] = 1.0f;
        atomicAdd(&g_hist[bk], 1);   // integer atomic: deterministic
    }
    __syncthreads();

    // -------- cooperative coalesced quantized_st + loss (scalar 32-bit) ----
    // out+OUT_Q is only 4B-aligned -> 32-bit stores, fully coalesced.
    double lsum = 0.0;
    float* oq = out + OUT_Q + (size_t)m0 * EMB_DIM;
    const float* xq = x + (size_t)m0 * EMB_DIM;
    for (int e = tid; e < BM * EMB_DIM; e += 256) {
        const int row = e >> 7;          // 0..127 (local)
        const int col = e & 127;
        const float xv = xq[e];
        const float qv = emb[(size_t)s_bk[row] * EMB_DIM + col];
        const float d  = __fsub_rn(qv, xv);
        oq[e] = __fadd_rn(xv, d);        // fl(x + fl(q-x)), exact STE math
        lsum += (double)d * (double)d;
    }
    lred[tid] = lsum;
    __syncthreads();
    for (int s = 128; s > 0; s >>= 1) {
        if (tid < s) lred[tid] += lred[tid + s];
        __syncthreads();
    }
    if (tid == 0) g_lpart[blockIdx.x] = lred[0];
}

// ---------------------------------------------------------------------------
// finalize: perplexity from histogram, loss from block partials
// ---------------------------------------------------------------------------
__global__ void vq_finalize_kernel(float* __restrict__ out) {
    __shared__ double sh[NUM_EMB];
    const int k = threadIdx.x;
    double p = (double)g_hist[k] / (double)N_TOKENS;
    sh[k] = p * log(p + 1e-10);
    __syncthreads();
    for (int s = NUM_EMB / 2; s > 0; s >>= 1) {
        if (k < s) sh[k] += sh[k + s];
        __syncthreads();
    }
    __shared__ double lacc[NUM_EMB];
    double ls = 0.0;
    for (int b = k; b < NBLK; b += NUM_EMB) ls += g_lpart[b];
    lacc[k] = ls;
    __syncthreads();
    for (int s = NUM_EMB / 2; s > 0; s >>= 1) {
        if (k < s) lacc[k] += lacc[k + s];
        __syncthreads();
    }
    if (k == 0) {
        out[OUT_PERP] = (float)exp(-sh[0]);
        out[OUT_LOSS] = (float)(lacc[0] / ((double)N_TOKENS * (double)EMB_DIM));
    }
}

// ---------------------------------------------------------------------------
extern "C" void kernel_launch(void* const* d_in, const int* in_sizes, int n_in,
                              void* d_out, int out_size) {
    const float* x   = (const float*)d_in[0];   // inputs [65536,128]
    const float* emb = (const float*)d_in[1];   // emb_w  [1024,128]
    float* out = (float*)d_out;

    vq_prep_kernel<<<(NUM_EMB + 255) / 256, 256>>>(emb);
    vq_sx_kernel<<<N_TOKENS / 8, 256>>>(x);
    vq_main_kernel<<<NBLK, 256>>>(x, emb, out);
    vq_finalize_kernel<<<1, NUM_EMB>>>(out);
}